// round 3
// baseline (speedup 1.0000x reference)
#include <cuda_runtime.h>
#include <cuda_bf16.h>
#include <math.h>

// Problem constants
#define TT 64
#define BB 32
#define HH 512
#define VV 32000
#define SS 64
#define MROWS (TT*BB)      // 2048
#define G4H (4*HH)         // 2048

// ---------------- scratch (static device allocations; no cudaMalloc) -------
__device__ float g_x   [MROWS*HH];     // embedded input [m,k]
__device__ float g_xw  [MROWS*G4H];    // input projection [m,g] (reused per layer)
__device__ float g_ys0 [MROWS*HH];     // layer0 outputs [m,k]
__device__ float g_ys1 [MROWS*HH];     // layer1 outputs (dec) [m,k]
__device__ float g_h0  [2][HH*BB];     // layer0 h ping-pong, transposed [j*32+b]
__device__ float g_h1  [2][HH*BB];     // layer1 h ping-pong
__device__ float g_c0  [HH*BB];        // layer0 c, transposed
__device__ float g_c1  [HH*BB];
__device__ float g_ctx [BB*HH];        // attention context (t-invariant)
__device__ float g_base[BB*VV];        // ctx @ W2b^T

// ---------------- init: transpose initial states ---------------------------
__global__ void init_state(const float* __restrict__ hidden,
                           const float* __restrict__ cell,
                           float* __restrict__ h0, float* __restrict__ h1,
                           float* __restrict__ c0, float* __restrict__ c1) {
    int idx = blockIdx.x * blockDim.x + threadIdx.x;   // 0..16383
    if (idx >= HH*BB) return;
    int j = idx >> 5, b = idx & 31;
    int src = b * HH + j;
    h0[idx] = hidden[src];
    h1[idx] = hidden[HH*BB + src];
    c0[idx] = cell[src];
    c1[idx] = cell[HH*BB + src];
}

// ---------------- embedding gather -----------------------------------------
__global__ void gather_emb(const int* __restrict__ tgt,
                           const float* __restrict__ emb,
                           float* __restrict__ x) {
    int m = blockIdx.x;                 // 0..2047
    int r = tgt[m];
    const float4* src = reinterpret_cast<const float4*>(emb + (size_t)r * HH);
    float4* dst = reinterpret_cast<float4*>(x + (size_t)m * HH);
    dst[threadIdx.x] = src[threadIdx.x];   // 128 threads x float4 = 512 floats
}

// ---------------- generic SGEMM: C[M,N] = A[M,K] * B[N,K]^T (+bias,+rowAdd) -
// 128x128 tile, 8x8 microtile, register-prefetched K pipeline.
__global__ __launch_bounds__(256)
void sgemm_nt(const float* __restrict__ A, int lda,
              const float* __restrict__ B, int ldb,
              float* __restrict__ C, int ldc,
              int M, int N, int K,
              const float* __restrict__ bias0,
              const float* __restrict__ bias1,
              const float* __restrict__ rowAdd, int rowMod) {
    __shared__ float As[8][128];
    __shared__ float Bs[8][128];
    int tid = threadIdx.x;
    int tx = tid & 15, ty = tid >> 4;
    int bm = blockIdx.y * 128, bn = blockIdx.x * 128;
    int lr = tid >> 1;              // 0..127
    int lc = (tid & 1) * 4;         // 0 or 4
    const float* Ap = A + (size_t)(bm + lr) * lda + lc;
    const float* Bp = B + (size_t)(bn + lr) * ldb + lc;
    bool aval = (bm + lr) < M;      // N tiles are always full in our shapes
    float acc[8][8];
    #pragma unroll
    for (int i = 0; i < 8; i++)
        #pragma unroll
        for (int j = 0; j < 8; j++) acc[i][j] = 0.f;

    // prefetch first K-tile
    float4 a4 = aval ? *reinterpret_cast<const float4*>(Ap)
                     : make_float4(0.f,0.f,0.f,0.f);
    float4 b4 = *reinterpret_cast<const float4*>(Bp);

    for (int k0 = 0; k0 < K; k0 += 8) {
        As[lc+0][lr] = a4.x; As[lc+1][lr] = a4.y;
        As[lc+2][lr] = a4.z; As[lc+3][lr] = a4.w;
        Bs[lc+0][lr] = b4.x; Bs[lc+1][lr] = b4.y;
        Bs[lc+2][lr] = b4.z; Bs[lc+3][lr] = b4.w;
        __syncthreads();
        // prefetch next K-tile while computing this one
        if (k0 + 8 < K) {
            a4 = aval ? *reinterpret_cast<const float4*>(Ap + k0 + 8)
                      : make_float4(0.f,0.f,0.f,0.f);
            b4 = *reinterpret_cast<const float4*>(Bp + k0 + 8);
        }
        #pragma unroll
        for (int kk = 0; kk < 8; kk++) {
            float ra[8], rb[8];
            *reinterpret_cast<float4*>(&ra[0]) = *reinterpret_cast<const float4*>(&As[kk][ty*8]);
            *reinterpret_cast<float4*>(&ra[4]) = *reinterpret_cast<const float4*>(&As[kk][ty*8+4]);
            *reinterpret_cast<float4*>(&rb[0]) = *reinterpret_cast<const float4*>(&Bs[kk][tx*8]);
            *reinterpret_cast<float4*>(&rb[4]) = *reinterpret_cast<const float4*>(&Bs[kk][tx*8+4]);
            #pragma unroll
            for (int i = 0; i < 8; i++)
                #pragma unroll
                for (int j = 0; j < 8; j++)
                    acc[i][j] = fmaf(ra[i], rb[j], acc[i][j]);
        }
        __syncthreads();
    }
    #pragma unroll
    for (int i = 0; i < 8; i++) {
        int r = bm + ty*8 + i;
        if (r >= M) continue;
        #pragma unroll
        for (int j = 0; j < 8; j++) {
            int cidx = bn + tx*8 + j;
            float v = acc[i][j];
            if (bias0)  v += bias0[cidx];
            if (bias1)  v += bias1[cidx];
            if (rowAdd) v += rowAdd[(size_t)(r % rowMod) * ldc + cidx];
            C[(size_t)r * ldc + cidx] = v;
        }
    }
}

// ---------------- one LSTM timestep -----------------------------------------
// grid = 128 CTAs, 128 threads. Thread = (gate-col j, batch b), computes all
// 4 gates for (b, j). h state is transposed [k*32+b] -> coalesced per warp.
__device__ __forceinline__ float sigmoidf_(float x) {
    return 1.f / (1.f + expf(-x));
}

__global__ __launch_bounds__(128)
void lstm_step(const float* __restrict__ xW,     // [2048, 2048]
               const float* __restrict__ W_hh,   // [2048, 512]
               const float* __restrict__ hT_in,  // [512*32]
               float* __restrict__ hT_out,       // [512*32]
               float* __restrict__ cT,           // [512*32] in-place
               float* __restrict__ ys,           // [2048, 512]
               int t) {
    int jj = threadIdx.x >> 5;
    int b  = threadIdx.x & 31;
    int j  = (blockIdx.x << 2) + jj;
    int m  = (t << 5) + b;

    const float* xr = xW + (size_t)m * G4H;
    float ai = xr[j];
    float af = xr[HH   + j];
    float ag = xr[2*HH + j];
    float ao = xr[3*HH + j];

    const float4* wi = reinterpret_cast<const float4*>(W_hh + (size_t)j        * HH);
    const float4* wf = reinterpret_cast<const float4*>(W_hh + (size_t)(HH+j)   * HH);
    const float4* wg = reinterpret_cast<const float4*>(W_hh + (size_t)(2*HH+j) * HH);
    const float4* wo = reinterpret_cast<const float4*>(W_hh + (size_t)(3*HH+j) * HH);

    #pragma unroll 4
    for (int k4 = 0; k4 < HH/4; ++k4) {
        float4 vi = wi[k4], vf = wf[k4], vg = wg[k4], vo = wo[k4];
        int k = k4 << 2;
        float h0 = hT_in[(k+0)*32 + b];
        float h1 = hT_in[(k+1)*32 + b];
        float h2 = hT_in[(k+2)*32 + b];
        float h3 = hT_in[(k+3)*32 + b];
        ai = fmaf(vi.x, h0, ai); af = fmaf(vf.x, h0, af);
        ag = fmaf(vg.x, h0, ag); ao = fmaf(vo.x, h0, ao);
        ai = fmaf(vi.y, h1, ai); af = fmaf(vf.y, h1, af);
        ag = fmaf(vg.y, h1, ag); ao = fmaf(vo.y, h1, ao);
        ai = fmaf(vi.z, h2, ai); af = fmaf(vf.z, h2, af);
        ag = fmaf(vg.z, h2, ag); ao = fmaf(vo.z, h2, ao);
        ai = fmaf(vi.w, h3, ai); af = fmaf(vf.w, h3, af);
        ag = fmaf(vg.w, h3, ag); ao = fmaf(vo.w, h3, ao);
    }

    float ig = sigmoidf_(ai);
    float fg = sigmoidf_(af);
    float gg = tanhf(ag);
    float og = sigmoidf_(ao);

    int sidx = j*32 + b;
    float c_new = fmaf(fg, cT[sidx], ig * gg);
    float h_new = og * tanhf(c_new);
    cT[sidx]     = c_new;
    hT_out[sidx] = h_new;
    ys[(size_t)m * HH + j] = h_new;
}

// ---------------- context: masked mean over S (exact softmax shortcut) ------
// scores[t,s,b,h] = NEG where mask, else att[t,b,h] (same value for every
// unmasked s) -> softmax over s is exactly uniform over unmasked positions
// (exp(NEG - att) underflows to 0.0f). Hence ctx = masked mean of enc_output,
// independent of t and of W1 entirely.
__global__ void ctx_kernel(const float* __restrict__ enc,
                           const int* __restrict__ src_mask,
                           float* __restrict__ ctx) {
    int b = blockIdx.x;       // 0..31
    int h = threadIdx.x;      // 0..511
    float s_un = 0.f, s_all = 0.f;
    int cnt = 0;
    #pragma unroll 4
    for (int s = 0; s < SS; s++) {
        float v = enc[((size_t)s * BB + b) * HH + h];
        int mk = src_mask[s * BB + b];
        s_all += v;
        if (mk == 0) { s_un += v; cnt++; }
    }
    ctx[b * HH + h] = (cnt > 0) ? (s_un * (1.f / (float)cnt))
                                : (s_all * (1.f / (float)SS));
}

// ---------------- tail: write hs, cs after the logits ------------------------
__global__ void tail_kernel(const float* __restrict__ ys0,
                            const float* __restrict__ ys1,
                            const float* __restrict__ c0,
                            const float* __restrict__ c1,
                            float* __restrict__ out) {
    int idx = blockIdx.x * blockDim.x + threadIdx.x;  // 0..65535
    if (idx >= 4*HH*BB) return;
    int seg = idx >> 14;          // 0:h_l0 1:h_l1 2:c_l0 3:c_l1
    int i   = idx & 16383;
    int b = i >> 9, j = i & 511;
    float v;
    if      (seg == 0) v = ys0[((size_t)(TT-1)*BB + b) * HH + j];
    else if (seg == 1) v = ys1[((size_t)(TT-1)*BB + b) * HH + j];
    else if (seg == 2) v = c0[j*32 + b];
    else               v = c1[j*32 + b];
    out[(size_t)MROWS * VV + idx] = v;
}

// ---------------- launch -----------------------------------------------------
extern "C" void kernel_launch(void* const* d_in, const int* in_sizes, int n_in,
                              void* d_out, int out_size) {
    (void)in_sizes; (void)n_in; (void)out_size;
    const int*   tgt     = (const int*)  d_in[0];
    const float* hidden  = (const float*)d_in[1];
    const float* cell    = (const float*)d_in[2];
    const float* enc     = (const float*)d_in[3];
    const int*   srcmask = (const int*)  d_in[4];
    const float* emb     = (const float*)d_in[5];
    const float* Wih0    = (const float*)d_in[6];
    const float* Whh0    = (const float*)d_in[7];
    const float* bih0    = (const float*)d_in[8];
    const float* bhh0    = (const float*)d_in[9];
    const float* Wih1    = (const float*)d_in[10];
    const float* Whh1    = (const float*)d_in[11];
    const float* bih1    = (const float*)d_in[12];
    const float* bhh1    = (const float*)d_in[13];
    // d_in[14] = W1 : provably irrelevant to output (softmax shortcut)
    const float* W2      = (const float*)d_in[15];
    float* out = (float*)d_out;

    float *p_x, *p_xw, *p_ys0, *p_ys1, *p_h0, *p_h1, *p_c0, *p_c1, *p_ctx, *p_base;
    cudaGetSymbolAddress((void**)&p_x,    g_x);
    cudaGetSymbolAddress((void**)&p_xw,   g_xw);
    cudaGetSymbolAddress((void**)&p_ys0,  g_ys0);
    cudaGetSymbolAddress((void**)&p_ys1,  g_ys1);
    cudaGetSymbolAddress((void**)&p_h0,   g_h0);
    cudaGetSymbolAddress((void**)&p_h1,   g_h1);
    cudaGetSymbolAddress((void**)&p_c0,   g_c0);
    cudaGetSymbolAddress((void**)&p_c1,   g_c1);
    cudaGetSymbolAddress((void**)&p_ctx,  g_ctx);
    cudaGetSymbolAddress((void**)&p_base, g_base);

    // 1. init recurrent state (transposed ping-pong buffers)
    init_state<<<64, 256>>>(hidden, cell, p_h0, p_h1, p_c0, p_c1);

    // 2. embedding gather
    gather_emb<<<MROWS, 128>>>(tgt, emb, p_x);

    // 3. input projection layer0: xw = x @ Wih0^T + bih0 + bhh0
    sgemm_nt<<<dim3(G4H/128, MROWS/128), 256>>>(p_x, HH, Wih0, HH, p_xw, G4H,
                                                MROWS, G4H, HH, bih0, bhh0, nullptr, 1);

    // 4. layer0 recurrence
    for (int t = 0; t < TT; t++) {
        lstm_step<<<128, 128>>>(p_xw, Whh0,
                                p_h0 + (t & 1) * HH*BB,
                                p_h0 + ((t + 1) & 1) * HH*BB,
                                p_c0, p_ys0, t);
    }

    // 5. input projection layer1
    sgemm_nt<<<dim3(G4H/128, MROWS/128), 256>>>(p_ys0, HH, Wih1, HH, p_xw, G4H,
                                                MROWS, G4H, HH, bih1, bhh1, nullptr, 1);

    // 6. layer1 recurrence
    for (int t = 0; t < TT; t++) {
        lstm_step<<<128, 128>>>(p_xw, Whh1,
                                p_h1 + (t & 1) * HH*BB,
                                p_h1 + ((t + 1) & 1) * HH*BB,
                                p_c1, p_ys1, t);
    }

    // 7. attention context (t-invariant masked mean)
    ctx_kernel<<<BB, HH>>>(enc, srcmask, p_ctx);

    // 8. base = ctx @ W2[:,512:]^T  -> [32, 32000]
    sgemm_nt<<<dim3(VV/128, 1), 256>>>(p_ctx, HH, W2 + HH, 2*HH, p_base, VV,
                                       BB, VV, HH, nullptr, nullptr, nullptr, 1);

    // 9. out = dec @ W2[:,:512]^T + base[b]  -> [2048, 32000]
    sgemm_nt<<<dim3(VV/128, MROWS/128), 256>>>(p_ys1, HH, W2, 2*HH, out, VV,
                                               MROWS, VV, HH, nullptr, nullptr, p_base, BB);

    // 10. hs / cs tail
    tail_kernel<<<64, 1024>>>(p_ys0, p_ys1, p_c0, p_c1, out);
}

// round 5
// speedup vs baseline: 2.4236x; 2.4236x over previous
#include <cuda_runtime.h>
#include <cuda_bf16.h>
#include <math.h>

// Problem constants
#define TT 64
#define BB 32
#define HH 512
#define VV 32000
#define SS 64
#define MROWS (TT*BB)      // 2048
#define G4H (4*HH)         // 2048

// ---------------- scratch (static device allocations; no cudaMalloc) -------
__device__ float g_x   [MROWS*HH];     // embedded input [m,k]
__device__ float g_xw  [MROWS*G4H];    // input projection, TRANSPOSED [gate_row][m]
__device__ float g_ys0 [MROWS*HH];     // layer0 outputs [m,k]
__device__ float g_ys1 [MROWS*HH];     // layer1 outputs (dec) [m,k]
__device__ float g_h0  [2][HH*BB];     // layer0 h ping-pong, transposed [j*32+b]
__device__ float g_h1  [2][HH*BB];     // layer1 h ping-pong
__device__ float g_c0  [HH*BB];        // layer0 c, transposed
__device__ float g_c1  [HH*BB];
__device__ float g_ctx [BB*HH];        // attention context (t-invariant)
__device__ float g_base[BB*VV];        // ctx @ W2b^T
__device__ int   g_bar [2*TT];         // grid-barrier counters (zeroed per launch)

// ---------------- init: transpose initial states + zero barrier counters ----
__global__ void init_state(const float* __restrict__ hidden,
                           const float* __restrict__ cell,
                           float* __restrict__ h0, float* __restrict__ h1,
                           float* __restrict__ c0, float* __restrict__ c1,
                           int* __restrict__ bar) {
    int idx = blockIdx.x * blockDim.x + threadIdx.x;   // 0..16383
    if (idx < 2*TT) bar[idx] = 0;
    if (idx >= HH*BB) return;
    int j = idx >> 5, b = idx & 31;
    int src = b * HH + j;
    h0[idx] = hidden[src];
    h1[idx] = hidden[HH*BB + src];
    c0[idx] = cell[src];
    c1[idx] = cell[HH*BB + src];
}

// ---------------- embedding gather -----------------------------------------
__global__ void gather_emb(const int* __restrict__ tgt,
                           const float* __restrict__ emb,
                           float* __restrict__ x) {
    int m = blockIdx.x;                 // 0..2047
    int r = tgt[m];
    const float4* src = reinterpret_cast<const float4*>(emb + (size_t)r * HH);
    float4* dst = reinterpret_cast<float4*>(x + (size_t)m * HH);
    dst[threadIdx.x] = src[threadIdx.x];   // 128 threads x float4 = 512 floats
}

// ---------------- generic SGEMM: C = A[M,K] * B[N,K]^T (+bias,+rowAdd) ------
// transC=0: C[r*ldc + n] (float4 stores);  transC=1: C[n*ldc + r]
__global__ __launch_bounds__(256)
void sgemm_nt(const float* __restrict__ A, int lda,
              const float* __restrict__ B, int ldb,
              float* __restrict__ C, int ldc,
              int M, int N, int K,
              const float* __restrict__ bias0,
              const float* __restrict__ bias1,
              const float* __restrict__ rowAdd, int rowMod,
              int transC) {
    __shared__ float As[8][128];
    __shared__ float Bs[8][128];
    int tid = threadIdx.x;
    int tx = tid & 15, ty = tid >> 4;
    int bm = blockIdx.y * 128, bn = blockIdx.x * 128;
    int lr = tid >> 1;              // 0..127
    int lc = (tid & 1) * 4;         // 0 or 4
    const float* Ap = A + (size_t)(bm + lr) * lda + lc;
    const float* Bp = B + (size_t)(bn + lr) * ldb + lc;
    bool aval = (bm + lr) < M;      // N tiles are always full in our shapes
    float acc[8][8];
    #pragma unroll
    for (int i = 0; i < 8; i++)
        #pragma unroll
        for (int j = 0; j < 8; j++) acc[i][j] = 0.f;

    // register-prefetch first K-tile
    float4 a4 = aval ? *reinterpret_cast<const float4*>(Ap)
                     : make_float4(0.f,0.f,0.f,0.f);
    float4 b4 = *reinterpret_cast<const float4*>(Bp);

    for (int k0 = 0; k0 < K; k0 += 8) {
        As[lc+0][lr] = a4.x; As[lc+1][lr] = a4.y;
        As[lc+2][lr] = a4.z; As[lc+3][lr] = a4.w;
        Bs[lc+0][lr] = b4.x; Bs[lc+1][lr] = b4.y;
        Bs[lc+2][lr] = b4.z; Bs[lc+3][lr] = b4.w;
        __syncthreads();
        if (k0 + 8 < K) {   // prefetch next tile while computing this one
            a4 = aval ? *reinterpret_cast<const float4*>(Ap + k0 + 8)
                      : make_float4(0.f,0.f,0.f,0.f);
            b4 = *reinterpret_cast<const float4*>(Bp + k0 + 8);
        }
        #pragma unroll
        for (int kk = 0; kk < 8; kk++) {
            float ra[8], rb[8];
            *reinterpret_cast<float4*>(&ra[0]) = *reinterpret_cast<const float4*>(&As[kk][ty*8]);
            *reinterpret_cast<float4*>(&ra[4]) = *reinterpret_cast<const float4*>(&As[kk][ty*8+4]);
            *reinterpret_cast<float4*>(&rb[0]) = *reinterpret_cast<const float4*>(&Bs[kk][tx*8]);
            *reinterpret_cast<float4*>(&rb[4]) = *reinterpret_cast<const float4*>(&Bs[kk][tx*8+4]);
            #pragma unroll
            for (int i = 0; i < 8; i++)
                #pragma unroll
                for (int j = 0; j < 8; j++)
                    acc[i][j] = fmaf(ra[i], rb[j], acc[i][j]);
        }
        __syncthreads();
    }
    #pragma unroll
    for (int i = 0; i < 8; i++) {
        int r = bm + ty*8 + i;
        if (r >= M) continue;
        if (!transC) {
            #pragma unroll
            for (int j0 = 0; j0 < 8; j0 += 4) {
                int cidx = bn + tx*8 + j0;
                float4 v = make_float4(acc[i][j0], acc[i][j0+1], acc[i][j0+2], acc[i][j0+3]);
                if (bias0) {
                    float4 t = *reinterpret_cast<const float4*>(bias0 + cidx);
                    v.x += t.x; v.y += t.y; v.z += t.z; v.w += t.w;
                }
                if (bias1) {
                    float4 t = *reinterpret_cast<const float4*>(bias1 + cidx);
                    v.x += t.x; v.y += t.y; v.z += t.z; v.w += t.w;
                }
                if (rowAdd) {
                    float4 t = *reinterpret_cast<const float4*>(
                        rowAdd + (size_t)(r % rowMod) * ldc + cidx);
                    v.x += t.x; v.y += t.y; v.z += t.z; v.w += t.w;
                }
                *reinterpret_cast<float4*>(C + (size_t)r * ldc + cidx) = v;
            }
        } else {
            #pragma unroll
            for (int j = 0; j < 8; j++) {
                int cidx = bn + tx*8 + j;
                float v = acc[i][j];
                if (bias0) v += bias0[cidx];
                if (bias1) v += bias1[cidx];
                C[(size_t)cidx * ldc + r] = v;
            }
        }
    }
}

// ---------------- persistent LSTM layer -------------------------------------
// grid = 128 CTAs x 128 threads; all CTAs co-resident (128 < 148 SMs).
// CTA c owns h-columns j in {4c..4c+3}. Warp w -> j_local, lane -> b.
// W slice (16 gate-rows x 512) lives in smem for the whole layer.
// h exchanged via global ping-pong + per-step arrive counters.
__device__ __forceinline__ float sigmoidf_(float x) {
    return 1.f / (1.f + expf(-x));
}

__global__ __launch_bounds__(128)
void lstm_persist(const float* __restrict__ xwT,   // [2048][2048] gate_row-major
                  const float* __restrict__ W_hh,  // [2048][512]
                  float* __restrict__ hbuf,        // [2][512*32] transposed
                  float* __restrict__ cbuf,        // [512*32]    transposed
                  float* __restrict__ ys,          // [2048][512]
                  int* __restrict__ bar)           // [TT] zeroed counters
{
    extern __shared__ float smem[];
    float* Ws = smem;            // [4 gates][4 j_local][512]  = 8192 floats
    float* Hs = smem + 4*4*HH;   // [512][32]                  = 16384 floats

    int tid = threadIdx.x;
    int w   = tid >> 5;          // j_local
    int b   = tid & 31;
    int cta = blockIdx.x;
    int jg  = cta * 4 + w;       // global h-column 0..511

    // Load this CTA's 16 gate-rows of W_hh into smem (once per layer).
    #pragma unroll
    for (int r = 0; r < 16; r++) {
        int g = r >> 2, jl = r & 3;
        const float4* src = reinterpret_cast<const float4*>(
            W_hh + (size_t)(g*HH + cta*4 + jl) * HH);
        float4* dst = reinterpret_cast<float4*>(&Ws[(g*4 + jl) * HH]);
        dst[tid] = src[tid];     // 128 float4 per row, one per thread
    }
    float creg = cbuf[jg*32 + b];
    __syncthreads();

    const float4* wi = reinterpret_cast<const float4*>(&Ws[(0*4 + w) * HH]);
    const float4* wf = reinterpret_cast<const float4*>(&Ws[(1*4 + w) * HH]);
    const float4* wg = reinterpret_cast<const float4*>(&Ws[(2*4 + w) * HH]);
    const float4* wo = reinterpret_cast<const float4*>(&Ws[(3*4 + w) * HH]);

    volatile int* vbar = (volatile int*)bar;

    for (int t = 0; t < TT; t++) {
        // stage h(t) into smem (L2-coherent loads; L1 may hold stale lines)
        {
            const float4* hsrc = reinterpret_cast<const float4*>(hbuf + (t & 1) * HH*BB);
            float4* hdst = reinterpret_cast<float4*>(Hs);
            #pragma unroll
            for (int i = 0; i < 32; i++)
                hdst[tid + (i << 7)] = __ldcg(hsrc + tid + (i << 7));
        }
        __syncthreads();

        int m = t*32 + b;
        float ai = xwT[(size_t)(0*HH + jg) * MROWS + m];
        float af = xwT[(size_t)(1*HH + jg) * MROWS + m];
        float ag = xwT[(size_t)(2*HH + jg) * MROWS + m];
        float ao = xwT[(size_t)(3*HH + jg) * MROWS + m];

        #pragma unroll 8
        for (int k4 = 0; k4 < HH/4; ++k4) {
            float4 vi = wi[k4], vf = wf[k4], vg = wg[k4], vo = wo[k4];
            int k = k4 << 2;
            float h0 = Hs[(k+0)*32 + b];
            float h1 = Hs[(k+1)*32 + b];
            float h2 = Hs[(k+2)*32 + b];
            float h3 = Hs[(k+3)*32 + b];
            ai = fmaf(vi.x, h0, ai); af = fmaf(vf.x, h0, af);
            ag = fmaf(vg.x, h0, ag); ao = fmaf(vo.x, h0, ao);
            ai = fmaf(vi.y, h1, ai); af = fmaf(vf.y, h1, af);
            ag = fmaf(vg.y, h1, ag); ao = fmaf(vo.y, h1, ao);
            ai = fmaf(vi.z, h2, ai); af = fmaf(vf.z, h2, af);
            ag = fmaf(vg.z, h2, ag); ao = fmaf(vo.z, h2, ao);
            ai = fmaf(vi.w, h3, ai); af = fmaf(vf.w, h3, af);
            ag = fmaf(vg.w, h3, ag); ao = fmaf(vo.w, h3, ao);
        }

        float ig = sigmoidf_(ai);
        float fg = sigmoidf_(af);
        float gg = tanhf(ag);
        float og = sigmoidf_(ao);
        float c_new = fmaf(fg, creg, ig * gg);
        float h_new = og * tanhf(c_new);
        creg = c_new;

        hbuf[((t+1) & 1) * HH*BB + jg*32 + b] = h_new;
        ys[(size_t)m * HH + jg] = h_new;
        if (t == TT-1) cbuf[jg*32 + b] = creg;

        // grid barrier: release writes, arrive, wait for all 128 CTAs
        __threadfence();
        __syncthreads();
        if (tid == 0) {
            atomicAdd(&bar[t], 1);
            while (vbar[t] < (int)gridDim.x) { __nanosleep(32); }
            __threadfence();
        }
        __syncthreads();
    }
}

// ---------------- context: masked mean over S (exact softmax shortcut) ------
// scores[t,s,b,h] = NEG where mask, else att[t,b,h] (same value for every
// unmasked s) -> softmax over s is exactly uniform over unmasked positions
// (exp(NEG - att) underflows to 0.0f). Hence ctx = masked mean of enc_output,
// independent of t and of W1 entirely.
__global__ void ctx_kernel(const float* __restrict__ enc,
                           const int* __restrict__ src_mask,
                           float* __restrict__ ctx) {
    int b = blockIdx.x;       // 0..31
    int h = threadIdx.x;      // 0..511
    float s_un = 0.f, s_all = 0.f;
    int cnt = 0;
    #pragma unroll 4
    for (int s = 0; s < SS; s++) {
        float v = enc[((size_t)s * BB + b) * HH + h];
        int mk = src_mask[s * BB + b];
        s_all += v;
        if (mk == 0) { s_un += v; cnt++; }
    }
    ctx[b * HH + h] = (cnt > 0) ? (s_un * (1.f / (float)cnt))
                                : (s_all * (1.f / (float)SS));
}

// ---------------- tail: write hs, cs after the logits ------------------------
__global__ void tail_kernel(const float* __restrict__ ys0,
                            const float* __restrict__ ys1,
                            const float* __restrict__ c0,
                            const float* __restrict__ c1,
                            float* __restrict__ out) {
    int idx = blockIdx.x * blockDim.x + threadIdx.x;  // 0..65535
    if (idx >= 4*HH*BB) return;
    int seg = idx >> 14;          // 0:h_l0 1:h_l1 2:c_l0 3:c_l1
    int i   = idx & 16383;
    int b = i >> 9, j = i & 511;
    float v;
    if      (seg == 0) v = ys0[((size_t)(TT-1)*BB + b) * HH + j];
    else if (seg == 1) v = ys1[((size_t)(TT-1)*BB + b) * HH + j];
    else if (seg == 2) v = c0[j*32 + b];
    else               v = c1[j*32 + b];
    out[(size_t)MROWS * VV + idx] = v;
}

// ---------------- launch -----------------------------------------------------
extern "C" void kernel_launch(void* const* d_in, const int* in_sizes, int n_in,
                              void* d_out, int out_size) {
    (void)in_sizes; (void)n_in; (void)out_size;
    const int*   tgt     = (const int*)  d_in[0];
    const float* hidden  = (const float*)d_in[1];
    const float* cell    = (const float*)d_in[2];
    const float* enc     = (const float*)d_in[3];
    const int*   srcmask = (const int*)  d_in[4];
    const float* emb     = (const float*)d_in[5];
    const float* Wih0    = (const float*)d_in[6];
    const float* Whh0    = (const float*)d_in[7];
    const float* bih0    = (const float*)d_in[8];
    const float* bhh0    = (const float*)d_in[9];
    const float* Wih1    = (const float*)d_in[10];
    const float* Whh1    = (const float*)d_in[11];
    const float* bih1    = (const float*)d_in[12];
    const float* bhh1    = (const float*)d_in[13];
    // d_in[14] = W1 : provably irrelevant to output (softmax shortcut)
    const float* W2      = (const float*)d_in[15];
    float* out = (float*)d_out;

    float *p_x, *p_xw, *p_ys0, *p_ys1, *p_h0, *p_h1, *p_c0, *p_c1, *p_ctx, *p_base;
    int *p_bar;
    cudaGetSymbolAddress((void**)&p_x,    g_x);
    cudaGetSymbolAddress((void**)&p_xw,   g_xw);
    cudaGetSymbolAddress((void**)&p_ys0,  g_ys0);
    cudaGetSymbolAddress((void**)&p_ys1,  g_ys1);
    cudaGetSymbolAddress((void**)&p_h0,   g_h0);
    cudaGetSymbolAddress((void**)&p_h1,   g_h1);
    cudaGetSymbolAddress((void**)&p_c0,   g_c0);
    cudaGetSymbolAddress((void**)&p_c1,   g_c1);
    cudaGetSymbolAddress((void**)&p_ctx,  g_ctx);
    cudaGetSymbolAddress((void**)&p_base, g_base);
    cudaGetSymbolAddress((void**)&p_bar,  g_bar);

    // no static guard (harness rule) — idempotent, cheap, capture-legal
    const int PERSIST_SMEM = (4*4*HH + HH*BB) * sizeof(float);  // 96 KB
    cudaFuncSetAttribute(lstm_persist,
                         cudaFuncAttributeMaxDynamicSharedMemorySize,
                         PERSIST_SMEM);

    // 1. init recurrent state (transposed ping-pong buffers) + zero barriers
    init_state<<<64, 256>>>(hidden, cell, p_h0, p_h1, p_c0, p_c1, p_bar);

    // 2. embedding gather
    gather_emb<<<MROWS, 128>>>(tgt, emb, p_x);

    // 3. input projection layer0 (transposed store): xwT = (x @ Wih0^T + b)^T
    sgemm_nt<<<dim3(G4H/128, MROWS/128), 256>>>(p_x, HH, Wih0, HH, p_xw, MROWS,
                                                MROWS, G4H, HH, bih0, bhh0,
                                                nullptr, 1, 1);

    // 4. layer0 recurrence (persistent, weights in smem)
    lstm_persist<<<128, 128, PERSIST_SMEM>>>(p_xw, Whh0, p_h0, p_c0, p_ys0, p_bar);

    // 5. input projection layer1 (transposed store)
    sgemm_nt<<<dim3(G4H/128, MROWS/128), 256>>>(p_ys0, HH, Wih1, HH, p_xw, MROWS,
                                                MROWS, G4H, HH, bih1, bhh1,
                                                nullptr, 1, 1);

    // 6. layer1 recurrence
    lstm_persist<<<128, 128, PERSIST_SMEM>>>(p_xw, Whh1, p_h1, p_c1, p_ys1, p_bar + TT);

    // 7. attention context (t-invariant masked mean)
    ctx_kernel<<<BB, HH>>>(enc, srcmask, p_ctx);

    // 8. base = ctx @ W2[:,512:]^T  -> [32, 32000]
    sgemm_nt<<<dim3(VV/128, 1), 256>>>(p_ctx, HH, W2 + HH, 2*HH, p_base, VV,
                                       BB, VV, HH, nullptr, nullptr, nullptr, 1, 0);

    // 9. out = dec @ W2[:,:512]^T + base[b]  -> [2048, 32000]
    sgemm_nt<<<dim3(VV/128, MROWS/128), 256>>>(p_ys1, HH, W2, 2*HH, out, VV,
                                               MROWS, VV, HH, nullptr, nullptr,
                                               p_base, BB, 0);

    // 10. hs / cs tail
    tail_kernel<<<64, 1024>>>(p_ys0, p_ys1, p_c0, p_c1, out);
}